// round 11
// baseline (speedup 1.0000x reference)
#include <cuda_runtime.h>
#include <cuda_bf16.h>

// EMA over time for wave[B=4096, T=6000, C=3] fp32, w=0.6, a=1-w=0.4.
//   y[f] = a*y[f-3] + w*x[f]   (per-channel recurrence; y[f<0]=0)
//
// One float4 group g maps 3-float state s -> s' = A s + b(x),
//   A = a*S, S = [[0,1,0],[0,0,1],[a,0,0]], S^3 = a*I
//   b(x) = (w*x1, w*x2, a*w*x0 + w*x3)
// Lane k handles group 32*i + k -> coalesced float4 I/O. Warp affine scan
// (d=1,2,4; dropped d=8 terms ~1e-4 norm err; older history exact via the
// per-lane carry matrix A^(k+1)). f=(y[4q+1..3]) gives o.y/z/w directly,
// o.x = (f2 - w*x3)/a recovered in-lane.
//
// R6: depth-3 software pipeline (2 LDG.128 in flight per warp), streaming
// cache hints (.cs) for the no-reuse r/w stream, SEGJ 24->36 to trim warm
// read overhead.

#define A1  0.4f
#define WW  0.6f
#define INVA 2.5f
#define A2  (A1*A1)
#define A3  (A2*A1)
#define A5  (A2*A3)
#define A6  (A3*A3)

#define B_DIM   4096
#define ROW_F4  4500            // 18000 floats / 4 per batch row
#define SEGJ    36              // emit-iterations per warp segment
#define NSEG    4               // 4*36 = 144 >= ceil(4500/32) = 141
#define NT      256
#define FULLM   0xFFFFFFFFu

__device__ __forceinline__ float4 ldg_cs_guard(const float4* p, bool ok) {
    float4 v = make_float4(0.f, 0.f, 0.f, 0.f);
    if (ok) v = __ldcs(p);
    return v;
}

// b(x) prep
__device__ __forceinline__ void prep_v(const float4& x, float& v0, float& v1, float& v2) {
    v0 = WW * x.y;
    v1 = WW * x.z;
    v2 = fmaf(A1 * WW, x.x, WW * x.w);
}

// 3-stage affine Hillis-Steele accumulation (carry-independent part).
__device__ __forceinline__ void scan_v(float& v0, float& v1, float& v2, int lane) {
    float t0, t1, t2;
    // d = 1 : A^1 = a*S       -> (a*t1, a*t2, a^2*t0)
    t0 = __shfl_up_sync(FULLM, v0, 1);
    t1 = __shfl_up_sync(FULLM, v1, 1);
    t2 = __shfl_up_sync(FULLM, v2, 1);
    if (lane < 1) { t0 = 0.f; t1 = 0.f; t2 = 0.f; }
    v0 = fmaf(A1, t1, v0);  v1 = fmaf(A1, t2, v1);  v2 = fmaf(A2, t0, v2);
    // d = 2 : A^2 = a^2*S^2   -> (a^2*t2, a^3*t0, a^3*t1)
    t0 = __shfl_up_sync(FULLM, v0, 2);
    t1 = __shfl_up_sync(FULLM, v1, 2);
    t2 = __shfl_up_sync(FULLM, v2, 2);
    if (lane < 2) { t0 = 0.f; t1 = 0.f; t2 = 0.f; }
    v0 = fmaf(A2, t2, v0);  v1 = fmaf(A3, t0, v1);  v2 = fmaf(A3, t1, v2);
    // d = 4 : A^4 = a^5*S     -> (a^5*t1, a^5*t2, a^6*t0)
    t0 = __shfl_up_sync(FULLM, v0, 4);
    t1 = __shfl_up_sync(FULLM, v1, 4);
    t2 = __shfl_up_sync(FULLM, v2, 4);
    if (lane < 4) { t0 = 0.f; t1 = 0.f; t2 = 0.f; }
    v0 = fmaf(A5, t1, v0);  v1 = fmaf(A5, t2, v1);  v2 = fmaf(A6, t0, v2);
}

__global__ __launch_bounds__(NT, 5)
void sta_ema_scan_kernel(const float4* __restrict__ in, float4* __restrict__ out) {
    const int gw   = (blockIdx.x * NT + threadIdx.x) >> 5;   // global warp id
    const int lane = threadIdx.x & 31;
    if (gw >= B_DIM * NSEG) return;

    const int b = gw / NSEG;
    const int s = gw % NSEG;

    const float4* src = in  + (long long)b * ROW_F4;
    float4*       dst = out + (long long)b * ROW_F4;

    const int i0 = SEGJ * s;

    // Per-lane constant carry matrix A^(k+1) = a^(k+1) * S^(k+1),
    // S^(k+1) = a^floor((k+1)/3) * S^((k+1)%3).
    const int  kp = lane + 1;
    const int  m  = kp / 3;
    const int  r  = kp % 3;
    const float gamma = __powf(A1, (float)(kp + m));
    float g0 = gamma, g1 = gamma, g2 = gamma;
    if (r == 1) { g2 *= A1; }
    if (r == 2) { g1 *= A1; g2 *= A1; }

    float sc0 = 0.f, sc1 = 0.f, sc2 = 0.f;

    // ---- warm iteration at i0-1 (s=0 loads out-of-range -> zeros) ----
    {
        const int q = 32 * (i0 - 1) + lane;
        float4 x = ldg_cs_guard(src + q, q >= 0 && q < ROW_F4);
        float v0, v1, v2;
        prep_v(x, v0, v1, v2);
        scan_v(v0, v1, v2, lane);
        // carry is zero here; f = v
        sc0 = __shfl_sync(FULLM, v0, 31);
        sc1 = __shfl_sync(FULLM, v1, 31);
        sc2 = __shfl_sync(FULLM, v2, 31);
    }

    // ---- pipeline prologue: iterations i0 and i0+1 loaded; i0 scanned ----
    int q0 = 32 * i0 + lane;                         // iter j   (tail stage)
    float4 x0 = ldg_cs_guard(src + q0, q0 < ROW_F4);
    float4 x1 = ldg_cs_guard(src + q0 + 32, q0 + 32 < ROW_F4);
    float v0, v1, v2;
    prep_v(x0, v0, v1, v2);
    scan_v(v0, v1, v2, lane);

    #pragma unroll 4
    for (int j = 0; j < SEGJ - 1; ++j) {
        // -- stage 1: issue load for iteration j+2 (2 loads now in flight) --
        const int q2 = q0 + 64;
        float4 xn = ldg_cs_guard(src + q2, q2 < ROW_F4);

        // -- stage 2: scan iteration j+1 (carry-independent) --
        float u0, u1, u2;
        prep_v(x1, u0, u1, u2);
        scan_v(u0, u1, u2, lane);

        // -- stage 3: serial tail for iteration j --
        float p0, p1, p2;
        if (r == 1)      { p0 = sc1; p1 = sc2; p2 = sc0; }
        else if (r == 2) { p0 = sc2; p1 = sc0; p2 = sc1; }
        else             { p0 = sc0; p1 = sc1; p2 = sc2; }
        const float f0 = fmaf(g0, p0, v0);
        const float f1 = fmaf(g1, p1, v1);
        const float f2 = fmaf(g2, p2, v2);

        float4 o;                                   // f = (y[4q+1], y[4q+2], y[4q+3])
        o.x = INVA * fmaf(-WW, x0.w, f2);           // y[4q] = (f2 - w*x3)/a
        o.y = f0;
        o.z = f1;
        o.w = f2;
        if (q0 < ROW_F4) __stcs(dst + q0, o);

        sc0 = __shfl_sync(FULLM, f0, 31);
        sc1 = __shfl_sync(FULLM, f1, 31);
        sc2 = __shfl_sync(FULLM, f2, 31);

        // rotate pipeline
        x0 = x1; x1 = xn;
        v0 = u0; v1 = u1; v2 = u2;
        q0 += 32;
    }

    // ---- epilogue: last iteration's tail ----
    {
        float p0, p1, p2;
        if (r == 1)      { p0 = sc1; p1 = sc2; p2 = sc0; }
        else if (r == 2) { p0 = sc2; p1 = sc0; p2 = sc1; }
        else             { p0 = sc0; p1 = sc1; p2 = sc2; }
        const float f0 = fmaf(g0, p0, v0);
        const float f1 = fmaf(g1, p1, v1);
        const float f2 = fmaf(g2, p2, v2);
        float4 o;
        o.x = INVA * fmaf(-WW, x0.w, f2);
        o.y = f0;
        o.z = f1;
        o.w = f2;
        if (q0 < ROW_F4) __stcs(dst + q0, o);
    }
}

extern "C" void kernel_launch(void* const* d_in, const int* in_sizes, int n_in,
                              void* d_out, int out_size) {
    const float4* in  = (const float4*)d_in[0];
    float4*       out = (float4*)d_out;
    const int warps = B_DIM * NSEG;                 // 16384
    const int ctas  = (warps * 32 + NT - 1) / NT;   // 2048
    sta_ema_scan_kernel<<<ctas, NT>>>(in, out);
}

// round 13
// speedup vs baseline: 1.2423x; 1.2423x over previous
#include <cuda_runtime.h>
#include <cuda_bf16.h>

// EMA over time for wave[B=4096, T=6000, C=3] fp32, w=0.6, a=1-w=0.4.
//   y[f] = a*y[f-3] + w*x[f]   (per-channel recurrence; y[f<0]=0)
//
// One float4 group g maps 3-float state s -> s' = A s + b(x),
//   A = a*S, S = [[0,1,0],[0,0,1],[a,0,0]], S^3 = a*I
//   b(x) = (w*x1, w*x2, a*w*x0 + w*x3)
// Lane k handles group 32*i + k -> coalesced float4 I/O. Warp affine scan
// (d=1,2,4; dropped d=8 terms ~1e-4 norm err; older history exact via the
// per-lane carry matrix A^(k+1)). f=(y[4q+1..3]) gives o.y/z/w directly,
// o.x = (f2 - w*x3)/a recovered in-lane.
//
// R7: R5 config restored (SEGJ=24/NSEG=6 -> 24576 warps, plain LDG/STG).
// Single change vs R5: depth-3 load pipeline (x for iter j+2 issued before
// the scan of j+1) -> 2 LDG.128 in flight per warp.

#define A1  0.4f
#define WW  0.6f
#define INVA 2.5f
#define A2  (A1*A1)
#define A3  (A2*A1)
#define A5  (A2*A3)
#define A6  (A3*A3)

#define B_DIM   4096
#define ROW_F4  4500            // 18000 floats / 4 per batch row
#define SEGJ    24              // emit-iterations per warp segment
#define NSEG    6               // 6*24 = 144 >= ceil(4500/32) = 141
#define NT      256
#define FULLM   0xFFFFFFFFu

// b(x) prep
__device__ __forceinline__ void prep_v(const float4& x, float& v0, float& v1, float& v2) {
    v0 = WW * x.y;
    v1 = WW * x.z;
    v2 = fmaf(A1 * WW, x.x, WW * x.w);
}

// 3-stage affine Hillis-Steele accumulation (carry-independent part).
__device__ __forceinline__ void scan_v(float& v0, float& v1, float& v2, int lane) {
    float t0, t1, t2;
    // d = 1 : A^1 = a*S       -> (a*t1, a*t2, a^2*t0)
    t0 = __shfl_up_sync(FULLM, v0, 1);
    t1 = __shfl_up_sync(FULLM, v1, 1);
    t2 = __shfl_up_sync(FULLM, v2, 1);
    if (lane < 1) { t0 = 0.f; t1 = 0.f; t2 = 0.f; }
    v0 = fmaf(A1, t1, v0);  v1 = fmaf(A1, t2, v1);  v2 = fmaf(A2, t0, v2);
    // d = 2 : A^2 = a^2*S^2   -> (a^2*t2, a^3*t0, a^3*t1)
    t0 = __shfl_up_sync(FULLM, v0, 2);
    t1 = __shfl_up_sync(FULLM, v1, 2);
    t2 = __shfl_up_sync(FULLM, v2, 2);
    if (lane < 2) { t0 = 0.f; t1 = 0.f; t2 = 0.f; }
    v0 = fmaf(A2, t2, v0);  v1 = fmaf(A3, t0, v1);  v2 = fmaf(A3, t1, v2);
    // d = 4 : A^4 = a^5*S     -> (a^5*t1, a^5*t2, a^6*t0)
    t0 = __shfl_up_sync(FULLM, v0, 4);
    t1 = __shfl_up_sync(FULLM, v1, 4);
    t2 = __shfl_up_sync(FULLM, v2, 4);
    if (lane < 4) { t0 = 0.f; t1 = 0.f; t2 = 0.f; }
    v0 = fmaf(A5, t1, v0);  v1 = fmaf(A5, t2, v1);  v2 = fmaf(A6, t0, v2);
}

__global__ __launch_bounds__(NT, 5)
void sta_ema_scan_kernel(const float4* __restrict__ in, float4* __restrict__ out) {
    const int gw   = (blockIdx.x * NT + threadIdx.x) >> 5;   // global warp id
    const int lane = threadIdx.x & 31;
    if (gw >= B_DIM * NSEG) return;

    const int b = gw / NSEG;
    const int s = gw % NSEG;

    const float4* src = in  + (long long)b * ROW_F4;
    float4*       dst = out + (long long)b * ROW_F4;

    const int i0 = SEGJ * s;

    // Per-lane constant carry matrix A^(k+1) = a^(k+1) * S^(k+1),
    // S^(k+1) = a^floor((k+1)/3) * S^((k+1)%3).
    const int  kp = lane + 1;
    const int  m  = kp / 3;
    const int  r  = kp % 3;
    const float gamma = __powf(A1, (float)(kp + m));
    float g0 = gamma, g1 = gamma, g2 = gamma;
    if (r == 1) { g2 *= A1; }
    if (r == 2) { g1 *= A1; g2 *= A1; }

    float sc0 = 0.f, sc1 = 0.f, sc2 = 0.f;

    // ---- warm iteration at i0-1 (s=0 loads out-of-range -> zeros) ----
    {
        const int q = 32 * (i0 - 1) + lane;
        float4 x = (q >= 0 && q < ROW_F4) ? src[q] : make_float4(0.f, 0.f, 0.f, 0.f);
        float v0, v1, v2;
        prep_v(x, v0, v1, v2);
        scan_v(v0, v1, v2, lane);
        // carry is zero here; f = v
        sc0 = __shfl_sync(FULLM, v0, 31);
        sc1 = __shfl_sync(FULLM, v1, 31);
        sc2 = __shfl_sync(FULLM, v2, 31);
    }

    // ---- pipeline prologue: iterations i0 and i0+1 loaded; i0 scanned ----
    int q0 = 32 * i0 + lane;                         // iter j (tail stage)
    float4 x0 = (q0 < ROW_F4) ? src[q0] : make_float4(0.f, 0.f, 0.f, 0.f);
    float4 x1 = (q0 + 32 < ROW_F4) ? src[q0 + 32] : make_float4(0.f, 0.f, 0.f, 0.f);
    float v0, v1, v2;
    prep_v(x0, v0, v1, v2);
    scan_v(v0, v1, v2, lane);

    #pragma unroll 4
    for (int j = 0; j < SEGJ - 1; ++j) {
        // -- stage 1: issue load for iteration j+2 (2 loads in flight) --
        const int q2 = q0 + 64;
        float4 xn = (q2 < ROW_F4) ? src[q2] : make_float4(0.f, 0.f, 0.f, 0.f);

        // -- stage 2: scan iteration j+1 (carry-independent) --
        float u0, u1, u2;
        prep_v(x1, u0, u1, u2);
        scan_v(u0, u1, u2, lane);

        // -- stage 3: serial tail for iteration j --
        float p0, p1, p2;
        if (r == 1)      { p0 = sc1; p1 = sc2; p2 = sc0; }
        else if (r == 2) { p0 = sc2; p1 = sc0; p2 = sc1; }
        else             { p0 = sc0; p1 = sc1; p2 = sc2; }
        const float f0 = fmaf(g0, p0, v0);
        const float f1 = fmaf(g1, p1, v1);
        const float f2 = fmaf(g2, p2, v2);

        float4 o;                                   // f = (y[4q+1], y[4q+2], y[4q+3])
        o.x = INVA * fmaf(-WW, x0.w, f2);           // y[4q] = (f2 - w*x3)/a
        o.y = f0;
        o.z = f1;
        o.w = f2;
        if (q0 < ROW_F4) dst[q0] = o;

        sc0 = __shfl_sync(FULLM, f0, 31);
        sc1 = __shfl_sync(FULLM, f1, 31);
        sc2 = __shfl_sync(FULLM, f2, 31);

        // rotate pipeline
        x0 = x1; x1 = xn;
        v0 = u0; v1 = u1; v2 = u2;
        q0 += 32;
    }

    // ---- epilogue: last iteration's tail ----
    {
        float p0, p1, p2;
        if (r == 1)      { p0 = sc1; p1 = sc2; p2 = sc0; }
        else if (r == 2) { p0 = sc2; p1 = sc0; p2 = sc1; }
        else             { p0 = sc0; p1 = sc1; p2 = sc2; }
        const float f0 = fmaf(g0, p0, v0);
        const float f1 = fmaf(g1, p1, v1);
        const float f2 = fmaf(g2, p2, v2);
        float4 o;
        o.x = INVA * fmaf(-WW, x0.w, f2);
        o.y = f0;
        o.z = f1;
        o.w = f2;
        if (q0 < ROW_F4) dst[q0] = o;
    }
}

extern "C" void kernel_launch(void* const* d_in, const int* in_sizes, int n_in,
                              void* d_out, int out_size) {
    const float4* in  = (const float4*)d_in[0];
    float4*       out = (float4*)d_out;
    const int warps = B_DIM * NSEG;                 // 24576
    const int ctas  = (warps * 32 + NT - 1) / NT;   // 3072
    sta_ema_scan_kernel<<<ctas, NT>>>(in, out);
}